// round 1
// baseline (speedup 1.0000x reference)
#include <cuda_runtime.h>
#include <cstdint>

#define BB   128   // batch
#define TT   2048  // time steps
#define DD   64    // input dim
#define HH   256   // hidden
#define OO   32    // output
#define KA   (DD + HH)   // 320 rows of concat [u;h]
#define NBLK 128
#define NTHR 256
#define KP   321   // padded A row (conflict-free smem)

// h ping-pong buffers + barrier state (static device scratch — no allocs)
__device__ float    g_h[2][BB * HH];
__device__ unsigned g_cnt;
__device__ volatile unsigned g_gen;

__global__ void lstm_reset_kernel() {
    g_cnt = 0u;
    g_gen = 0u;
}

__device__ __forceinline__ float sigf(float x) {
    return 1.0f / (1.0f + __expf(-x));
}
__device__ __forceinline__ float tanh_fast(float x) {
    // tanh(x) = 1 - 2/(e^{2x}+1); exact at 0, saturates correctly at +-inf
    return 1.0f - 2.0f / (__expf(2.0f * x) + 1.0f);
}

__device__ __forceinline__ void grid_bar(unsigned target) {
    __threadfence();
    __syncthreads();
    if (threadIdx.x == 0) {
        unsigned arrived = atomicAdd(&g_cnt, 1u);
        if (arrived == NBLK - 1u) {
            g_cnt = 0u;            // reset for next barrier (no one arrives until release)
            __threadfence();
            g_gen = target;        // release
        } else {
            while (g_gen < target) { }
        }
    }
    __syncthreads();
}

__global__ void __launch_bounds__(NTHR, 1)
lstm_main_kernel(const float* __restrict__ u,
                 const float* __restrict__ x0,
                 const float* __restrict__ kfiz,
                 const float* __restrict__ bfiz,
                 const float* __restrict__ kr,
                 const float* __restrict__ br,
                 const float* __restrict__ Wout,
                 const float* __restrict__ bout,
                 float* __restrict__ out)
{
    extern __shared__ float smem[];
    float* A_sh    = smem;                    // [BB][KP]  = 41088 f
    float* Wg      = A_sh + BB * KP;          // [KA][8]   = 2560 f
    float* Wout_sh = Wg + KA * 8;             // [HH*OO]   = 8192 f
    float* g_sh    = Wout_sh + HH * OO;       // [BB][9]   = 1152 f
    float* c_sh    = g_sh + BB * 9;           // [256]
    float* hy_sh   = c_sh + 256;              // [256]
    float* ysum    = hy_sh + 256;             // [256]
    float* bias_sh = ysum + 256;              // [8]
    float* bo_sh   = bias_sh + 8;             // [32]

    const int tid = threadIdx.x;
    const int bid = blockIdx.x;
    const int j0  = bid * 2;

    // ---- one-time init: weights slice, biases, Wout, c, h0 ----
    for (int idx = tid; idx < KA * 8; idx += NTHR) {
        int k = idx >> 3, o = idx & 7;
        int gate = o >> 1, jj = o & 1;
        Wg[idx] = (gate < 3) ? kfiz[k * (3 * HH) + gate * HH + j0 + jj]
                             : kr[k * HH + j0 + jj];
    }
    if (tid < 8) {
        int gate = tid >> 1, jj = tid & 1;
        bias_sh[tid] = (gate < 3) ? bfiz[gate * HH + j0 + jj] : br[j0 + jj];
    }
    if (tid < OO) bo_sh[tid] = bout[tid];
    for (int idx = tid; idx < HH * OO; idx += NTHR) Wout_sh[idx] = Wout[idx];
    {   // c0 for this block's two hidden units, all batches
        int b = tid >> 1, jj = tid & 1;
        c_sh[tid] = x0[b * (2 * HH) + HH + j0 + jj];
    }
    // block bid publishes h0 for batch bid
    for (int j = tid; j < HH; j += NTHR)
        g_h[0][bid * HH + j] = x0[bid * (2 * HH) + j];

    grid_bar(1u);

    const int b_mine  = tid & 127;        // batch this thread computes gates for
    const int obase   = (tid >> 7) * 4;   // 0 -> {f0,f1,i0,i1}, 4 -> {z0,z1,r0,r1}
    const float* arow = A_sh + b_mine * KP;

#pragma unroll 1
    for (int t = 0; t < TT; ++t) {
        const int cur = t & 1;
        const int nxt = cur ^ 1;

        // ---- stage A = [u_t ; h_prev], transposed into padded rows ----
        for (int idx = tid; idx < (BB * DD) / 4; idx += NTHR) {
            int b  = idx >> 4;
            int kq = (idx & 15) << 2;
            float4 v = *(const float4*)(u + ((size_t)b * TT + t) * DD + kq);
            float* dst = A_sh + b * KP + kq;
            dst[0] = v.x; dst[1] = v.y; dst[2] = v.z; dst[3] = v.w;
        }
        for (int idx = tid; idx < (BB * HH) / 4; idx += NTHR) {
            int b  = idx >> 6;
            int kq = (idx & 63) << 2;
            float4 v = __ldcg((const float4*)(g_h[cur] + b * HH + kq));
            float* dst = A_sh + b * KP + DD + kq;
            dst[0] = v.x; dst[1] = v.y; dst[2] = v.z; dst[3] = v.w;
        }
        __syncthreads();

        // ---- gate GEMM: 4 dots of length 320 per thread ----
        float acc0 = bias_sh[obase + 0];
        float acc1 = bias_sh[obase + 1];
        float acc2 = bias_sh[obase + 2];
        float acc3 = bias_sh[obase + 3];
#pragma unroll 8
        for (int k = 0; k < KA; ++k) {
            float  a = arow[k];
            float4 w = *(const float4*)(Wg + k * 8 + obase);
            acc0 = fmaf(a, w.x, acc0);
            acc1 = fmaf(a, w.y, acc1);
            acc2 = fmaf(a, w.z, acc2);
            acc3 = fmaf(a, w.w, acc3);
        }
        if (obase == 0) {               // f0 f1 i0 i1 : sigmoid
            acc0 = sigf(acc0); acc1 = sigf(acc1);
            acc2 = sigf(acc2); acc3 = sigf(acc3);
        } else {                        // z0 z1 : sigmoid ; r0 r1 : tanh
            acc0 = sigf(acc0); acc1 = sigf(acc1);
            acc2 = tanh_fast(acc2); acc3 = tanh_fast(acc3);
        }
        {
            float* gr = g_sh + b_mine * 9 + obase;
            gr[0] = acc0; gr[1] = acc1; gr[2] = acc2; gr[3] = acc3;
        }
        __syncthreads();

        // ---- c/h update for my 2 hidden units x 128 batches ----
        {
            int bb = tid >> 1, jj = tid & 1;
            const float* gr = g_sh + bb * 9;
            float f = gr[0 + jj], i = gr[2 + jj], z = gr[4 + jj], r = gr[6 + jj];
            float c = fmaf(f, c_sh[tid], i * r);
            c_sh[tid] = c;
            g_h[nxt][bb * HH + j0 + jj] = z * tanh_fast(c);
        }

        grid_bar((unsigned)(t + 2));

        // ---- y_t for batch = bid (h_new now globally visible) ----
        if (tid < HH / 4) {
            float4 hv = __ldcg((const float4*)(g_h[nxt] + bid * HH) + tid);
            ((float4*)hy_sh)[tid] = hv;
        }
        __syncthreads();
        {
            int o = tid & 31, ks = tid >> 5;
            const float* hb = hy_sh + ks * 32;
            const float* wb = Wout_sh + ks * 32 * OO + o;
            float p = 0.f;
#pragma unroll
            for (int kk = 0; kk < 32; ++kk)
                p = fmaf(hb[kk], wb[kk * OO], p);
            ysum[tid] = p;
        }
        __syncthreads();
        if (tid < OO) {
            float y = bo_sh[tid];
#pragma unroll
            for (int s = 0; s < 8; ++s) y += ysum[s * 32 + tid];
            out[((size_t)bid * TT + t) * OO + tid] = y;
        }
        __syncthreads();   // protect hy_sh/ysum/A_sh before next iteration
    }
}

extern "C" void kernel_launch(void* const* d_in, const int* in_sizes, int n_in,
                              void* d_out, int out_size)
{
    const float* u    = (const float*)d_in[0];
    const float* x0   = (const float*)d_in[1];
    const float* kfiz = (const float*)d_in[2];
    const float* bfiz = (const float*)d_in[3];
    const float* kr   = (const float*)d_in[4];
    const float* br   = (const float*)d_in[5];
    const float* Wout = (const float*)d_in[6];
    const float* bout = (const float*)d_in[7];
    float* out = (float*)d_out;

    const size_t smem_bytes =
        (size_t)(BB * KP + KA * 8 + HH * OO + BB * 9 + 256 + 256 + 256 + 8 + 32)
        * sizeof(float);   // 215,200 B

    cudaFuncSetAttribute(lstm_main_kernel,
                         cudaFuncAttributeMaxDynamicSharedMemorySize,
                         (int)smem_bytes);

    lstm_reset_kernel<<<1, 1>>>();
    lstm_main_kernel<<<NBLK, NTHR, smem_bytes>>>(u, x0, kfiz, bfiz, kr, br,
                                                 Wout, bout, out);
}